// round 15
// baseline (speedup 1.0000x reference)
#include <cuda_runtime.h>
#include <cuda_fp16.h>
#include <cstdint>
#include <cstddef>

constexpr int B = 4, C = 16, H = 512, W = 960;
constexpr int HW   = H * W;
constexpr int NPIX = B * HW;           // 1,966,080

// Quad-plane geometry for the metric accumulator.
constexpr int QW = W / 2 + 1;          // 481
constexpr int QH = H / 2 + 1;          // 257
constexpr size_t QPLANE = (size_t)B * QH * QW;
constexpr int QU = W / 2;              // 480
constexpr int QV = H / 2;              // 256
constexpr int NQUADS = B * QV * QU;    // 491,520

constexpr int THREADS = 256;

// Accumulation scratch, zero-initialized at module load; each call restores zeros.
__device__ __align__(32) __half2 g_vals[(size_t)NPIX * 8];   // [pix][16ch fp16], 32B rows
__device__ __align__(16) float  g_metq[4 * QPLANE * 4];      // [plane][b][qy][qx][4]

// Grid barrier state. Generation counter is monotonic across calls/replays,
// so no per-call reset is needed (count returns to 0 at every release).
__device__ volatile unsigned g_bar_gen = 0;
__device__ unsigned g_bar_count = 0;

__device__ __forceinline__ void grid_barrier(unsigned nblocks) {
    __threadfence();          // make this thread's reds/stores GPU-visible
    __syncthreads();
    if (threadIdx.x == 0) {
        const unsigned gen = g_bar_gen;
        const unsigned old = atomicAdd(&g_bar_count, 1);
        if (old == nblocks - 1) {
            g_bar_count = 0;
            __threadfence();
            g_bar_gen = gen + 1;              // release
        } else {
            while (g_bar_gen == gen) __nanosleep(64);
        }
    }
    __syncthreads();
    __threadfence();          // acquire side: order subsequent loads
}

__device__ __forceinline__ void red_add_v4h2(__half2* p, uint32_t a, uint32_t b,
                                             uint32_t c, uint32_t d) {
    asm volatile("red.global.add.noftz.v4.f16x2 [%0], {%1, %2, %3, %4};"
                 :: "l"(p), "r"(a), "r"(b), "r"(c), "r"(d) : "memory");
}
__device__ __forceinline__ void red_add_v4f(float* p, float a, float b, float c, float d) {
    asm volatile("red.global.add.v4.f32 [%0], {%1, %2, %3, %4};"
                 :: "l"(p), "f"(a), "f"(b), "f"(c), "f"(d) : "memory");
}
__device__ __forceinline__ uint32_t pack2(float lo, float hi) {
    __half2 h = __floats2half2_rn(lo, hi);
    return *reinterpret_cast<uint32_t*>(&h);
}

__device__ __forceinline__ void splat_pixel(int idx,
                                            const float* __restrict__ in,
                                            const float* __restrict__ flow,
                                            const float* __restrict__ metric) {
    int b = idx / HW;
    int p = idx - b * HW;
    int y = p / W;
    int x = p - y * W;

    const float fx = (float)x + __ldcs(flow + (size_t)b * 2 * HW + p);
    const float fy = (float)y + __ldcs(flow + (size_t)b * 2 * HW + HW + p);
    const float m  = __expf(__ldcs(metric + idx));

    const float x0f = floorf(fx), y0f = floorf(fy);
    const int   x0  = (int)x0f,   y0  = (int)y0f;
    const float wx1 = fx - x0f, wy1 = fy - y0f;
    const float wx0 = 1.0f - wx1, wy0 = 1.0f - wy1;

    const bool vx0 = (unsigned)x0       < (unsigned)W;
    const bool vx1 = (unsigned)(x0 + 1) < (unsigned)W;
    const bool vy0 = (unsigned)y0       < (unsigned)H;
    const bool vy1 = (unsigned)(y0 + 1) < (unsigned)H;

    // ---- metric: ONE v4.f32 red into the parity-matched quad plane ----
    {
        const float w00 = (vx0 && vy0) ? wx0 * wy0 : 0.0f;
        const float w10 = (vx1 && vy0) ? wx1 * wy0 : 0.0f;
        const float w01 = (vx0 && vy1) ? wx0 * wy1 : 0.0f;
        const float w11 = (vx1 && vy1) ? wx1 * wy1 : 0.0f;
        const int cx0 = min(max(x0, -1), W - 1);
        const int cy0 = min(max(y0, -1), H - 1);
        const int pl  = (cy0 & 1) * 2 + (cx0 & 1);
        const int qx  = (cx0 >> 1) + 1;
        const int qy  = (cy0 >> 1) + 1;
        float* slot = g_metq + ((size_t)pl * QPLANE
                                + ((size_t)b * QH + qy) * QW + qx) * 4;
        red_add_v4f(slot, m * w00, m * w10, m * w01, m * w11);
    }

    // ---- channels: 2 x v4.f16x2 per valid corner ----
    float v[16];
    const float* inp = in + (size_t)b * C * HW + p;
#pragma unroll
    for (int c = 0; c < 16; ++c) v[c] = __ldcs(inp + (size_t)c * HW) * m;

#pragma unroll
    for (int cy = 0; cy < 2; ++cy) {
        const int yi = y0 + cy;
        if ((unsigned)yi >= (unsigned)H) continue;
        const float wy = cy ? wy1 : wy0;
#pragma unroll
        for (int cx = 0; cx < 2; ++cx) {
            const int xi = x0 + cx;
            if ((unsigned)xi >= (unsigned)W) continue;
            const float w = wy * (cx ? wx1 : wx0);
            const size_t d = (size_t)b * HW + (size_t)yi * W + xi;
            __half2* dst = g_vals + d * 8;
            uint32_t r0 = pack2(v[0]  * w, v[1]  * w);
            uint32_t r1 = pack2(v[2]  * w, v[3]  * w);
            uint32_t r2 = pack2(v[4]  * w, v[5]  * w);
            uint32_t r3 = pack2(v[6]  * w, v[7]  * w);
            uint32_t r4 = pack2(v[8]  * w, v[9]  * w);
            uint32_t r5 = pack2(v[10] * w, v[11] * w);
            uint32_t r6 = pack2(v[12] * w, v[13] * w);
            uint32_t r7 = pack2(v[14] * w, v[15] * w);
            red_add_v4h2(dst + 0, r0, r1, r2, r3);
            red_add_v4h2(dst + 4, r4, r5, r6, r7);
        }
    }
}

__device__ __forceinline__ void normq_quad(int t, float* __restrict__ out) {
    const int u = t % QU;
    const int r = t / QU;
    const int v = r % QV;
    const int b = r / QV;

    const float4* mq = reinterpret_cast<const float4*>(g_metq);
    float4*       mw = reinterpret_cast<float4*>(g_metq);
    auto Q = [&](int pl, int qy, int qx) -> size_t {
        return (size_t)pl * QPLANE + ((size_t)b * QH + qy) * QW + qx;
    };
    const size_t iA   = Q(0, v + 1, u + 1);
    const size_t iBm  = Q(1, v + 1, u    );
    const size_t iBp  = Q(1, v + 1, u + 1);
    const size_t iCm  = Q(2, v,     u + 1);
    const size_t iCp  = Q(2, v + 1, u + 1);
    const size_t iDmm = Q(3, v,     u    );
    const size_t iDpm = Q(3, v,     u + 1);
    const size_t iDmp = Q(3, v + 1, u    );
    const size_t iDpp = Q(3, v + 1, u + 1);

    const float4 A   = mq[iA];
    const float4 Bm  = mq[iBm];
    const float4 Bp  = mq[iBp];
    const float4 Cm  = mq[iCm];
    const float4 Cp  = mq[iCp];
    const float4 Dmm = mq[iDmm];
    const float4 Dpm = mq[iDpm];
    const float4 Dmp = mq[iDmp];
    const float4 Dpp = mq[iDpp];

    const size_t p00 = (size_t)b * HW + (size_t)(2 * v) * W + 2 * u;
    uint4* s0 = reinterpret_cast<uint4*>(g_vals + p00 * 8);
    uint4* s1 = reinterpret_cast<uint4*>(g_vals + (p00 + W) * 8);
    const uint4 q00a = s0[0], q00b = s0[1], q10a = s0[2], q10b = s0[3];
    const uint4 q01a = s1[0], q01b = s1[1], q11a = s1[2], q11b = s1[3];

    // ---- owner-exact zeroing of everything this thread read ----
    mw[iA] = make_float4(0.f, 0.f, 0.f, 0.f);
    g_metq[iBm * 4 + 1] = 0.0f;
    g_metq[iBm * 4 + 3] = 0.0f;
    g_metq[iBp * 4 + 0] = 0.0f;
    g_metq[iBp * 4 + 2] = 0.0f;
    *reinterpret_cast<float2*>(g_metq + iCm * 4 + 2) = make_float2(0.f, 0.f);
    *reinterpret_cast<float2*>(g_metq + iCp * 4 + 0) = make_float2(0.f, 0.f);
    g_metq[iDmm * 4 + 3] = 0.0f;
    g_metq[iDpm * 4 + 2] = 0.0f;
    g_metq[iDmp * 4 + 1] = 0.0f;
    g_metq[iDpp * 4 + 0] = 0.0f;

    const float d00 = A.x + Bm.y + Cm.z + Dmm.w;
    const float d10 = A.y + Bp.x + Cm.w + Dpm.z;
    const float d01 = A.z + Bm.w + Cp.x + Dmp.y;
    const float d11 = A.w + Bp.z + Cp.y + Dpp.x;
    const float i00 = 1.0f / (d00 + 1e-7f);
    const float i10 = 1.0f / (d10 + 1e-7f);
    const float i01 = 1.0f / (d01 + 1e-7f);
    const float i11 = 1.0f / (d11 + 1e-7f);

    const uint32_t h00[8] = {q00a.x, q00a.y, q00a.z, q00a.w, q00b.x, q00b.y, q00b.z, q00b.w};
    const uint32_t h10[8] = {q10a.x, q10a.y, q10a.z, q10a.w, q10b.x, q10b.y, q10b.z, q10b.w};
    const uint32_t h01[8] = {q01a.x, q01a.y, q01a.z, q01a.w, q01b.x, q01b.y, q01b.z, q01b.w};
    const uint32_t h11[8] = {q11a.x, q11a.y, q11a.z, q11a.w, q11b.x, q11b.y, q11b.z, q11b.w};

    float* o = out + (size_t)b * C * HW + (size_t)(2 * v) * W + 2 * u;
#pragma unroll
    for (int q = 0; q < 8; ++q) {
        const float2 f00 = __half22float2(*reinterpret_cast<const __half2*>(&h00[q]));
        const float2 f10 = __half22float2(*reinterpret_cast<const __half2*>(&h10[q]));
        const float2 f01 = __half22float2(*reinterpret_cast<const __half2*>(&h01[q]));
        const float2 f11 = __half22float2(*reinterpret_cast<const __half2*>(&h11[q]));
        float* oc0 = o + (size_t)(2 * q)     * HW;
        float* oc1 = o + (size_t)(2 * q + 1) * HW;
        __stcs(reinterpret_cast<float2*>(oc0),     make_float2(f00.x * i00, f10.x * i10));
        __stcs(reinterpret_cast<float2*>(oc1),     make_float2(f00.y * i00, f10.y * i10));
        __stcs(reinterpret_cast<float2*>(oc0 + W), make_float2(f01.x * i01, f11.x * i11));
        __stcs(reinterpret_cast<float2*>(oc1 + W), make_float2(f01.y * i01, f11.y * i11));
    }

    const uint4 z = make_uint4(0u, 0u, 0u, 0u);
    s0[0] = z; s0[1] = z; s0[2] = z; s0[3] = z;
    s1[0] = z; s1[1] = z; s1[2] = z; s1[3] = z;
}

// Persistent fused kernel: splat phase -> grid barrier -> normalize phase.
// Grid is sized to exact residency on the host, so the barrier cannot deadlock.
__global__ void __launch_bounds__(THREADS)
fused_kernel(const float* __restrict__ in,
             const float* __restrict__ flow,
             const float* __restrict__ metric,
             float* __restrict__ out) {
    const unsigned nblocks = gridDim.x;
    const int      stride  = nblocks * THREADS;

    for (int idx = blockIdx.x * THREADS + threadIdx.x; idx < NPIX; idx += stride)
        splat_pixel(idx, in, flow, metric);

    grid_barrier(nblocks);

    for (int t = blockIdx.x * THREADS + threadIdx.x; t < NQUADS; t += stride)
        normq_quad(t, out);
}

extern "C" void kernel_launch(void* const* d_in, const int* in_sizes, int n_in,
                              void* d_out, int out_size) {
    const float* ten_in     = (const float*)d_in[0];
    const float* ten_flow   = (const float*)d_in[1];
    const float* ten_metric = (const float*)d_in[2];
    float* out = (float*)d_out;

    int dev = 0;
    cudaGetDevice(&dev);
    int num_sms = 0;
    cudaDeviceGetAttribute(&num_sms, cudaDevAttrMultiProcessorCount, dev);
    int blocks_per_sm = 0;
    cudaOccupancyMaxActiveBlocksPerMultiprocessor(&blocks_per_sm, fused_kernel,
                                                  THREADS, 0);
    if (blocks_per_sm < 1) blocks_per_sm = 1;
    int grid = num_sms * blocks_per_sm;
    if (grid > (NQUADS + THREADS - 1) / THREADS)
        grid = (NQUADS + THREADS - 1) / THREADS;

    fused_kernel<<<grid, THREADS>>>(ten_in, ten_flow, ten_metric, out);
}

// round 16
// speedup vs baseline: 1.0741x; 1.0741x over previous
#include <cuda_runtime.h>
#include <cuda_fp16.h>
#include <cstdint>
#include <cstddef>

constexpr int B = 4, C = 16, H = 512, W = 960;
constexpr int HW   = H * W;
constexpr int NPIX = B * HW;           // 1,966,080

// Quad-plane geometry for the metric accumulator.
constexpr int QW = W / 2 + 1;          // 481
constexpr int QH = H / 2 + 1;          // 257
constexpr size_t QPLANE = (size_t)B * QH * QW;
constexpr int QU = W / 2;              // 480
constexpr int QV = H / 2;              // 256
constexpr int UP = QU / 2;             // 240 quad-pairs per row
constexpr int NPAIRS = B * QV * UP;    // 245,760

// Accumulation scratch, zero-initialized at module load; each call restores zeros.
__device__ __align__(32) __half2 g_vals[(size_t)NPIX * 8];   // [pix][16ch fp16], 32B rows
__device__ __align__(16) float  g_metq[4 * QPLANE * 4];      // [plane][b][qy][qx][4]

__device__ __forceinline__ void red_add_v4h2(__half2* p, uint32_t a, uint32_t b,
                                             uint32_t c, uint32_t d) {
    asm volatile("red.global.add.noftz.v4.f16x2 [%0], {%1, %2, %3, %4};"
                 :: "l"(p), "r"(a), "r"(b), "r"(c), "r"(d) : "memory");
}
__device__ __forceinline__ void red_add_v4f(float* p, float a, float b, float c, float d) {
    asm volatile("red.global.add.v4.f32 [%0], {%1, %2, %3, %4};"
                 :: "l"(p), "f"(a), "f"(b), "f"(c), "f"(d) : "memory");
}
__device__ __forceinline__ uint32_t pack2(float lo, float hi) {
    __half2 h = __floats2half2_rn(lo, hi);
    return *reinterpret_cast<uint32_t*>(&h);
}

__global__ void __launch_bounds__(256)
splat_kernel(const float* __restrict__ in,
             const float* __restrict__ flow,
             const float* __restrict__ metric) {
    int idx = blockIdx.x * blockDim.x + threadIdx.x;
    if (idx >= NPIX) return;
    int b = idx / HW;
    int p = idx - b * HW;
    int y = p / W;
    int x = p - y * W;

    const float fx = (float)x + __ldcs(flow + (size_t)b * 2 * HW + p);
    const float fy = (float)y + __ldcs(flow + (size_t)b * 2 * HW + HW + p);
    const float m  = __expf(__ldcs(metric + idx));

    const float x0f = floorf(fx), y0f = floorf(fy);
    const int   x0  = (int)x0f,   y0  = (int)y0f;
    const float wx1 = fx - x0f, wy1 = fy - y0f;
    const float wx0 = 1.0f - wx1, wy0 = 1.0f - wy1;

    const bool vx0 = (unsigned)x0       < (unsigned)W;
    const bool vx1 = (unsigned)(x0 + 1) < (unsigned)W;
    const bool vy0 = (unsigned)y0       < (unsigned)H;
    const bool vy1 = (unsigned)(y0 + 1) < (unsigned)H;

    // ---- metric: ONE v4.f32 red into the parity-matched quad plane ----
    {
        const float w00 = (vx0 && vy0) ? wx0 * wy0 : 0.0f;
        const float w10 = (vx1 && vy0) ? wx1 * wy0 : 0.0f;
        const float w01 = (vx0 && vy1) ? wx0 * wy1 : 0.0f;
        const float w11 = (vx1 && vy1) ? wx1 * wy1 : 0.0f;
        const int cx0 = min(max(x0, -1), W - 1);
        const int cy0 = min(max(y0, -1), H - 1);
        const int pl  = (cy0 & 1) * 2 + (cx0 & 1);
        const int qx  = (cx0 >> 1) + 1;
        const int qy  = (cy0 >> 1) + 1;
        float* slot = g_metq + ((size_t)pl * QPLANE
                                + ((size_t)b * QH + qy) * QW + qx) * 4;
        red_add_v4f(slot, m * w00, m * w10, m * w01, m * w11);
    }

    // ---- channels: 2 x v4.f16x2 per valid corner ----
    float v[16];
    const float* inp = in + (size_t)b * C * HW + p;
#pragma unroll
    for (int c = 0; c < 16; ++c) v[c] = __ldcs(inp + (size_t)c * HW) * m;

#pragma unroll
    for (int cy = 0; cy < 2; ++cy) {
        const int yi = y0 + cy;
        if ((unsigned)yi >= (unsigned)H) continue;
        const float wy = cy ? wy1 : wy0;
#pragma unroll
        for (int cx = 0; cx < 2; ++cx) {
            const int xi = x0 + cx;
            if ((unsigned)xi >= (unsigned)W) continue;
            const float w = wy * (cx ? wx1 : wx0);
            const size_t d = (size_t)b * HW + (size_t)yi * W + xi;
            __half2* dst = g_vals + d * 8;
            uint32_t r0 = pack2(v[0]  * w, v[1]  * w);
            uint32_t r1 = pack2(v[2]  * w, v[3]  * w);
            uint32_t r2 = pack2(v[4]  * w, v[5]  * w);
            uint32_t r3 = pack2(v[6]  * w, v[7]  * w);
            uint32_t r4 = pack2(v[8]  * w, v[9]  * w);
            uint32_t r5 = pack2(v[10] * w, v[11] * w);
            uint32_t r6 = pack2(v[12] * w, v[13] * w);
            uint32_t r7 = pack2(v[14] * w, v[15] * w);
            red_add_v4h2(dst + 0, r0, r1, r2, r3);
            red_add_v4h2(dst + 4, r4, r5, r6, r7);
        }
    }
}

// Fused collapse + normalize, one thread per TWO x-adjacent output quads
// (4 pixels wide x 2 rows). Adjacent quads share plane-1/3 gather quads:
// 15 float4 gathers (vs 18), output stores are float4 (4 x-adjacent pixels).
// Owner-exact zeroing extended to the pair (middle plane-1 quad becomes a
// full exclusive float4).
__global__ void __launch_bounds__(256)
normq_kernel(float* __restrict__ out) {
    int t = blockIdx.x * blockDim.x + threadIdx.x;
    if (t >= NPAIRS) return;
    const int up = t % UP;
    const int r  = t / UP;
    const int v  = r % QV;
    const int b  = r / QV;
    const int u0 = 2 * up;

    const float4* mq = reinterpret_cast<const float4*>(g_metq);
    float4*       mw = reinterpret_cast<float4*>(g_metq);
    auto Q = [&](int pl, int qy, int qx) -> size_t {
        return (size_t)pl * QPLANE + ((size_t)b * QH + qy) * QW + qx;
    };

    // ---- metq gather: 15 coalesced float4 (batched for MLP) ----
    const size_t iA0  = Q(0, v + 1, u0 + 1);
    const size_t iA1  = Q(0, v + 1, u0 + 2);
    const size_t iB0  = Q(1, v + 1, u0    );
    const size_t iB1  = Q(1, v + 1, u0 + 1);
    const size_t iB2  = Q(1, v + 1, u0 + 2);
    const size_t iCm0 = Q(2, v,     u0 + 1);
    const size_t iCm1 = Q(2, v,     u0 + 2);
    const size_t iCp0 = Q(2, v + 1, u0 + 1);
    const size_t iCp1 = Q(2, v + 1, u0 + 2);
    const size_t iDm0 = Q(3, v,     u0    );
    const size_t iDm1 = Q(3, v,     u0 + 1);
    const size_t iDm2 = Q(3, v,     u0 + 2);
    const size_t iDp0 = Q(3, v + 1, u0    );
    const size_t iDp1 = Q(3, v + 1, u0 + 1);
    const size_t iDp2 = Q(3, v + 1, u0 + 2);

    const float4 A0  = mq[iA0];
    const float4 A1  = mq[iA1];
    const float4 B0  = mq[iB0];
    const float4 B1  = mq[iB1];
    const float4 B2  = mq[iB2];
    const float4 Cm0 = mq[iCm0];
    const float4 Cm1 = mq[iCm1];
    const float4 Cp0 = mq[iCp0];
    const float4 Cp1 = mq[iCp1];
    const float4 Dm0 = mq[iDm0];
    const float4 Dm1 = mq[iDm1];
    const float4 Dm2 = mq[iDm2];
    const float4 Dp0 = mq[iDp0];
    const float4 Dp1 = mq[iDp1];
    const float4 Dp2 = mq[iDp2];

    // ---- channel scratch: 4 pixels x 2 rows, fully contiguous per row ----
    const size_t p00 = (size_t)b * HW + (size_t)(2 * v) * W + 2 * u0;
    uint4* s0 = reinterpret_cast<uint4*>(g_vals + p00 * 8);
    uint4* s1 = reinterpret_cast<uint4*>(g_vals + (p00 + W) * 8);
    uint4 r0[8], r1[8];
#pragma unroll
    for (int k = 0; k < 8; ++k) r0[k] = s0[k];
#pragma unroll
    for (int k = 0; k < 8; ++k) r1[k] = s1[k];

    // ---- owner-exact zeroing of everything this thread read ----
    const float4 zf4 = make_float4(0.f, 0.f, 0.f, 0.f);
    const float2 zf2 = make_float2(0.f, 0.f);
    mw[iA0] = zf4;                       // plane 0: exclusive quads
    mw[iA1] = zf4;
    mw[iB1] = zf4;                       // plane 1 middle: both halves owned
    g_metq[iB0 * 4 + 1] = 0.0f;          // plane 1 edges
    g_metq[iB0 * 4 + 3] = 0.0f;
    g_metq[iB2 * 4 + 0] = 0.0f;
    g_metq[iB2 * 4 + 2] = 0.0f;
    *reinterpret_cast<float2*>(g_metq + iCm0 * 4 + 2) = zf2;   // plane 2
    *reinterpret_cast<float2*>(g_metq + iCm1 * 4 + 2) = zf2;
    *reinterpret_cast<float2*>(g_metq + iCp0 * 4 + 0) = zf2;
    *reinterpret_cast<float2*>(g_metq + iCp1 * 4 + 0) = zf2;
    *reinterpret_cast<float2*>(g_metq + iDm1 * 4 + 2) = zf2;   // plane 3 middle
    *reinterpret_cast<float2*>(g_metq + iDp1 * 4 + 0) = zf2;
    g_metq[iDm0 * 4 + 3] = 0.0f;         // plane 3 edges
    g_metq[iDm2 * 4 + 2] = 0.0f;
    g_metq[iDp0 * 4 + 1] = 0.0f;
    g_metq[iDp2 * 4 + 0] = 0.0f;

    // ---- denominators: 8 pixels ----
    const float i00  = 1.0f / ((A0.x + B0.y + Cm0.z + Dm0.w) + 1e-7f);
    const float i10  = 1.0f / ((A0.y + B1.x + Cm0.w + Dm1.z) + 1e-7f);
    const float i01  = 1.0f / ((A0.z + B0.w + Cp0.x + Dp0.y) + 1e-7f);
    const float i11  = 1.0f / ((A0.w + B1.z + Cp0.y + Dp1.x) + 1e-7f);
    const float i00b = 1.0f / ((A1.x + B1.y + Cm1.z + Dm1.w) + 1e-7f);
    const float i10b = 1.0f / ((A1.y + B2.x + Cm1.w + Dm2.z) + 1e-7f);
    const float i01b = 1.0f / ((A1.z + B1.w + Cp1.x + Dp1.y) + 1e-7f);
    const float i11b = 1.0f / ((A1.w + B2.z + Cp1.y + Dp2.x) + 1e-7f);

    // ---- normalize + write: float4 stores (4 x-adjacent pixels/channel) ----
    const uint32_t* w0 = reinterpret_cast<const uint32_t*>(r0);  // px j -> w0[j*8+q]
    const uint32_t* w1 = reinterpret_cast<const uint32_t*>(r1);
    float* o = out + (size_t)b * C * HW + (size_t)(2 * v) * W + 2 * u0;
#pragma unroll
    for (int q = 0; q < 8; ++q) {   // half2 q holds channels 2q, 2q+1
        const float2 a = __half22float2(*reinterpret_cast<const __half2*>(&w0[q]));
        const float2 bq= __half22float2(*reinterpret_cast<const __half2*>(&w0[8 + q]));
        const float2 c = __half22float2(*reinterpret_cast<const __half2*>(&w0[16 + q]));
        const float2 d = __half22float2(*reinterpret_cast<const __half2*>(&w0[24 + q]));
        const float2 e = __half22float2(*reinterpret_cast<const __half2*>(&w1[q]));
        const float2 f = __half22float2(*reinterpret_cast<const __half2*>(&w1[8 + q]));
        const float2 g = __half22float2(*reinterpret_cast<const __half2*>(&w1[16 + q]));
        const float2 h = __half22float2(*reinterpret_cast<const __half2*>(&w1[24 + q]));
        float* oc0 = o + (size_t)(2 * q)     * HW;
        float* oc1 = o + (size_t)(2 * q + 1) * HW;
        __stcs(reinterpret_cast<float4*>(oc0),
               make_float4(a.x * i00, bq.x * i10, c.x * i00b, d.x * i10b));
        __stcs(reinterpret_cast<float4*>(oc1),
               make_float4(a.y * i00, bq.y * i10, c.y * i00b, d.y * i10b));
        __stcs(reinterpret_cast<float4*>(oc0 + W),
               make_float4(e.x * i01, f.x * i11, g.x * i01b, h.x * i11b));
        __stcs(reinterpret_cast<float4*>(oc1 + W),
               make_float4(e.y * i01, f.y * i11, g.y * i01b, h.y * i11b));
    }

    // Restore zeros in channel scratch (exclusive rows).
    const uint4 z = make_uint4(0u, 0u, 0u, 0u);
#pragma unroll
    for (int k = 0; k < 8; ++k) s0[k] = z;
#pragma unroll
    for (int k = 0; k < 8; ++k) s1[k] = z;
}

extern "C" void kernel_launch(void* const* d_in, const int* in_sizes, int n_in,
                              void* d_out, int out_size) {
    const float* ten_in     = (const float*)d_in[0];
    const float* ten_flow   = (const float*)d_in[1];
    const float* ten_metric = (const float*)d_in[2];
    float* out = (float*)d_out;

    const int threads = 256;
    splat_kernel<<<(NPIX + threads - 1) / threads, threads>>>(ten_in, ten_flow, ten_metric);
    normq_kernel<<<(NPAIRS + threads - 1) / threads, threads>>>(out);
}

// round 17
// speedup vs baseline: 1.2476x; 1.1615x over previous
#include <cuda_runtime.h>
#include <cuda_fp16.h>
#include <cstdint>
#include <cstddef>

constexpr int B = 4, C = 16, H = 512, W = 960;
constexpr int HW   = H * W;
constexpr int NPIX = B * HW;           // 1,966,080

// Quad-plane geometry for the metric accumulator.
constexpr int QW = W / 2 + 1;          // 481
constexpr int QH = H / 2 + 1;          // 257
constexpr size_t QPLANE = (size_t)B * QH * QW;
constexpr int QU = W / 2;              // 480
constexpr int QV = H / 2;              // 256
constexpr int NQUADS = B * QV * QU;    // 491,520

// Accumulation scratch, zero-initialized at module load; each call restores zeros.
__device__ __align__(32) __half2 g_vals[(size_t)NPIX * 8];   // [pix][16ch fp16], 32B rows
__device__ __align__(16) float  g_metq[4 * QPLANE * 4];      // [plane][b][qy][qx][4]

__device__ __forceinline__ void red_add_v4h2(__half2* p, uint32_t a, uint32_t b,
                                             uint32_t c, uint32_t d) {
    asm volatile("red.global.add.noftz.v4.f16x2 [%0], {%1, %2, %3, %4};"
                 :: "l"(p), "r"(a), "r"(b), "r"(c), "r"(d) : "memory");
}
__device__ __forceinline__ void red_add_v4f(float* p, float a, float b, float c, float d) {
    asm volatile("red.global.add.v4.f32 [%0], {%1, %2, %3, %4};"
                 :: "l"(p), "f"(a), "f"(b), "f"(c), "f"(d) : "memory");
}
__device__ __forceinline__ uint32_t pack2(float lo, float hi) {
    __half2 h = __floats2half2_rn(lo, hi);
    return *reinterpret_cast<uint32_t*>(&h);
}

__global__ void __launch_bounds__(256)
splat_kernel(const float* __restrict__ in,
             const float* __restrict__ flow,
             const float* __restrict__ metric) {
    int idx = blockIdx.x * blockDim.x + threadIdx.x;
    if (idx >= NPIX) return;
    int b = idx / HW;
    int p = idx - b * HW;
    int y = p / W;
    int x = p - y * W;

    const float fx = (float)x + __ldcs(flow + (size_t)b * 2 * HW + p);
    const float fy = (float)y + __ldcs(flow + (size_t)b * 2 * HW + HW + p);
    const float m  = __expf(__ldcs(metric + idx));

    const float x0f = floorf(fx), y0f = floorf(fy);
    const int   x0  = (int)x0f,   y0  = (int)y0f;
    const float wx1 = fx - x0f, wy1 = fy - y0f;
    const float wx0 = 1.0f - wx1, wy0 = 1.0f - wy1;

    const bool vx0 = (unsigned)x0       < (unsigned)W;
    const bool vx1 = (unsigned)(x0 + 1) < (unsigned)W;
    const bool vy0 = (unsigned)y0       < (unsigned)H;
    const bool vy1 = (unsigned)(y0 + 1) < (unsigned)H;

    // ---- metric: ONE v4.f32 red into the parity-matched quad plane ----
    {
        const float w00 = (vx0 && vy0) ? wx0 * wy0 : 0.0f;
        const float w10 = (vx1 && vy0) ? wx1 * wy0 : 0.0f;
        const float w01 = (vx0 && vy1) ? wx0 * wy1 : 0.0f;
        const float w11 = (vx1 && vy1) ? wx1 * wy1 : 0.0f;
        const int cx0 = min(max(x0, -1), W - 1);
        const int cy0 = min(max(y0, -1), H - 1);
        const int pl  = (cy0 & 1) * 2 + (cx0 & 1);
        const int qx  = (cx0 >> 1) + 1;
        const int qy  = (cy0 >> 1) + 1;
        float* slot = g_metq + ((size_t)pl * QPLANE
                                + ((size_t)b * QH + qy) * QW + qx) * 4;
        red_add_v4f(slot, m * w00, m * w10, m * w01, m * w11);
    }

    // ---- channels: 2 x v4.f16x2 per valid corner ----
    float v[16];
    const float* inp = in + (size_t)b * C * HW + p;
#pragma unroll
    for (int c = 0; c < 16; ++c) v[c] = __ldcs(inp + (size_t)c * HW) * m;

#pragma unroll
    for (int cy = 0; cy < 2; ++cy) {
        const int yi = y0 + cy;
        if ((unsigned)yi >= (unsigned)H) continue;
        const float wy = cy ? wy1 : wy0;
#pragma unroll
        for (int cx = 0; cx < 2; ++cx) {
            const int xi = x0 + cx;
            if ((unsigned)xi >= (unsigned)W) continue;
            const float w = wy * (cx ? wx1 : wx0);
            const size_t d = (size_t)b * HW + (size_t)yi * W + xi;
            __half2* dst = g_vals + d * 8;
            uint32_t r0 = pack2(v[0]  * w, v[1]  * w);
            uint32_t r1 = pack2(v[2]  * w, v[3]  * w);
            uint32_t r2 = pack2(v[4]  * w, v[5]  * w);
            uint32_t r3 = pack2(v[6]  * w, v[7]  * w);
            uint32_t r4 = pack2(v[8]  * w, v[9]  * w);
            uint32_t r5 = pack2(v[10] * w, v[11] * w);
            uint32_t r6 = pack2(v[12] * w, v[13] * w);
            uint32_t r7 = pack2(v[14] * w, v[15] * w);
            red_add_v4h2(dst + 0, r0, r1, r2, r3);
            red_add_v4h2(dst + 4, r4, r5, r6, r7);
        }
    }
}

// Fused collapse + normalize, one thread per aligned 2x2 output quad.
// LIFO traversal: first blocks process the LAST-written scratch (hottest in
// L2 after splat), converting DRAM reads to L2 hits.
__global__ void __launch_bounds__(256)
normq_kernel(float* __restrict__ out) {
    int t0 = blockIdx.x * blockDim.x + threadIdx.x;
    if (t0 >= NQUADS) return;
    const int t = NQUADS - 1 - t0;     // reverse order; lanes stay consecutive
    const int u = t % QU;
    const int r = t / QU;
    const int v = r % QV;
    const int b = r / QV;

    const float4* mq = reinterpret_cast<const float4*>(g_metq);
    float4*       mw = reinterpret_cast<float4*>(g_metq);
    auto Q = [&](int pl, int qy, int qx) -> size_t {
        return (size_t)pl * QPLANE + ((size_t)b * QH + qy) * QW + qx;
    };
    const size_t iA   = Q(0, v + 1, u + 1);
    const size_t iBm  = Q(1, v + 1, u    );
    const size_t iBp  = Q(1, v + 1, u + 1);
    const size_t iCm  = Q(2, v,     u + 1);
    const size_t iCp  = Q(2, v + 1, u + 1);
    const size_t iDmm = Q(3, v,     u    );
    const size_t iDpm = Q(3, v,     u + 1);
    const size_t iDmp = Q(3, v + 1, u    );
    const size_t iDpp = Q(3, v + 1, u + 1);

    const float4 A   = mq[iA];
    const float4 Bm  = mq[iBm];
    const float4 Bp  = mq[iBp];
    const float4 Cm  = mq[iCm];
    const float4 Cp  = mq[iCp];
    const float4 Dmm = mq[iDmm];
    const float4 Dpm = mq[iDpm];
    const float4 Dmp = mq[iDmp];
    const float4 Dpp = mq[iDpp];

    // Channel scratch: row 2v holds pixels (2u, 2u+1) contiguously (32B each).
    const size_t p00 = (size_t)b * HW + (size_t)(2 * v) * W + 2 * u;
    uint4* s0 = reinterpret_cast<uint4*>(g_vals + p00 * 8);
    uint4* s1 = reinterpret_cast<uint4*>(g_vals + (p00 + W) * 8);
    const uint4 q00a = s0[0], q00b = s0[1], q10a = s0[2], q10b = s0[3];
    const uint4 q01a = s1[0], q01b = s1[1], q11a = s1[2], q11b = s1[3];

    // ---- owner-exact zeroing of everything this thread read ----
    mw[iA] = make_float4(0.f, 0.f, 0.f, 0.f);       // plane 0: exclusive quad
    g_metq[iBm * 4 + 1] = 0.0f;                     // plane 1: elems {1,3} of Bm
    g_metq[iBm * 4 + 3] = 0.0f;
    g_metq[iBp * 4 + 0] = 0.0f;                     //          elems {0,2} of Bp
    g_metq[iBp * 4 + 2] = 0.0f;
    *reinterpret_cast<float2*>(g_metq + iCm * 4 + 2) = make_float2(0.f, 0.f);  // Cm {2,3}
    *reinterpret_cast<float2*>(g_metq + iCp * 4 + 0) = make_float2(0.f, 0.f);  // Cp {0,1}
    g_metq[iDmm * 4 + 3] = 0.0f;                    // plane 3: one elem each
    g_metq[iDpm * 4 + 2] = 0.0f;
    g_metq[iDmp * 4 + 1] = 0.0f;
    g_metq[iDpp * 4 + 0] = 0.0f;

    const float d00 = A.x + Bm.y + Cm.z + Dmm.w;
    const float d10 = A.y + Bp.x + Cm.w + Dpm.z;
    const float d01 = A.z + Bm.w + Cp.x + Dmp.y;
    const float d11 = A.w + Bp.z + Cp.y + Dpp.x;
    const float i00 = 1.0f / (d00 + 1e-7f);
    const float i10 = 1.0f / (d10 + 1e-7f);
    const float i01 = 1.0f / (d01 + 1e-7f);
    const float i11 = 1.0f / (d11 + 1e-7f);

    const uint32_t h00[8] = {q00a.x, q00a.y, q00a.z, q00a.w, q00b.x, q00b.y, q00b.z, q00b.w};
    const uint32_t h10[8] = {q10a.x, q10a.y, q10a.z, q10a.w, q10b.x, q10b.y, q10b.z, q10b.w};
    const uint32_t h01[8] = {q01a.x, q01a.y, q01a.z, q01a.w, q01b.x, q01b.y, q01b.z, q01b.w};
    const uint32_t h11[8] = {q11a.x, q11a.y, q11a.z, q11a.w, q11b.x, q11b.y, q11b.z, q11b.w};

    float* o = out + (size_t)b * C * HW + (size_t)(2 * v) * W + 2 * u;
#pragma unroll
    for (int q = 0; q < 8; ++q) {   // half2 q holds channels 2q, 2q+1
        const float2 f00 = __half22float2(*reinterpret_cast<const __half2*>(&h00[q]));
        const float2 f10 = __half22float2(*reinterpret_cast<const __half2*>(&h10[q]));
        const float2 f01 = __half22float2(*reinterpret_cast<const __half2*>(&h01[q]));
        const float2 f11 = __half22float2(*reinterpret_cast<const __half2*>(&h11[q]));
        float* oc0 = o + (size_t)(2 * q)     * HW;
        float* oc1 = o + (size_t)(2 * q + 1) * HW;
        __stcs(reinterpret_cast<float2*>(oc0),     make_float2(f00.x * i00, f10.x * i10));
        __stcs(reinterpret_cast<float2*>(oc1),     make_float2(f00.y * i00, f10.y * i10));
        __stcs(reinterpret_cast<float2*>(oc0 + W), make_float2(f01.x * i01, f11.x * i11));
        __stcs(reinterpret_cast<float2*>(oc1 + W), make_float2(f01.y * i01, f11.y * i11));
    }

    // Restore zeros in channel scratch (exclusive rows; default policy so the
    // zeroed lines linger in L2 for the next call's reds).
    const uint4 z = make_uint4(0u, 0u, 0u, 0u);
    s0[0] = z; s0[1] = z; s0[2] = z; s0[3] = z;
    s1[0] = z; s1[1] = z; s1[2] = z; s1[3] = z;
}

extern "C" void kernel_launch(void* const* d_in, const int* in_sizes, int n_in,
                              void* d_out, int out_size) {
    const float* ten_in     = (const float*)d_in[0];
    const float* ten_flow   = (const float*)d_in[1];
    const float* ten_metric = (const float*)d_in[2];
    float* out = (float*)d_out;

    const int threads = 256;
    splat_kernel<<<(NPIX + threads - 1) / threads, threads>>>(ten_in, ten_flow, ten_metric);
    normq_kernel<<<(NQUADS + threads - 1) / threads, threads>>>(out);
}